// round 13
// baseline (speedup 1.0000x reference)
#include <cuda_runtime.h>
#include <cstdint>

#define NN 4096
#define BB 32

// ---------------- scratch (device globals) ----------------
__device__ __align__(512) char g_maskT[4096u * 4096u];          // int8 0/1, 16 MB
__device__ __align__(512) char g_hhi[2048u * 4096u];            // s8 hi plane, 8 MB
__device__ __align__(512) unsigned char g_hlo[2048u * 4096u];   // u8 lo plane, 8 MB
__device__ float g_score1[BB * NN];
__device__ float g_hsumPart[BB * 32 * 64];
__device__ float g_hsum[BB * 64];

__device__ __forceinline__ uint32_t smem_u32(const void* p) {
    uint32_t a;
    asm("{ .reg .u64 t; cvta.to.shared.u64 t, %1; cvt.u32.u64 %0, t; }" : "=r"(a) : "l"(p));
    return a;
}
__device__ __forceinline__ void cpa16(uint32_t s, const void* g) {
    asm volatile("cp.async.cg.shared.global [%0], [%1], 16;\n" :: "r"(s), "l"(g) : "memory");
}

// ============================================================================
// k_prep: h = inp@W (row0 zeroed) -> int16 quantize -> hi/lo byte planes.
// score1 computed in a 2nd pass from the QUANTIZED h (no warp shuffles in main
// loop).  grid(32 b, 32 jb) x 256 thr, dyn smem 101632 (2 CTAs/SM)
// ============================================================================
__global__ void __launch_bounds__(256) k_prep(const float* __restrict__ inp,
                                              const float* __restrict__ W,
                                              const float* __restrict__ a)
{
    extern __shared__ char sm[];
    float* sW  = (float*)sm;                            // [64][64]    16384
    float* sIn = (float*)(sm + 16384);                  // [128][64]   32768
    float* sA1 = (float*)(sm + 49152);                  // [64][129]   33024
    char*  sHi = sm + 82176;                            // [64][144]    9216
    unsigned char* sLo = (unsigned char*)(sm + 91392);  // [64][144]    9216
    float* sHs = (float*)(sm + 100608);                 // [4][64]      1024

    const int b = blockIdx.x, jb = blockIdx.y;
    const int tid = threadIdx.x;

    const float4* W4 = (const float4*)W;
    float4* sW4 = (float4*)sW;
    for (int t = tid; t < 1024; t += 256) sW4[t] = W4[t];
    const float4* I4 = (const float4*)(inp + ((long)b * NN + jb * 128) * 64);
    float4* sI4 = (float4*)sIn;
    for (int t = tid; t < 2048; t += 256) sI4[t] = I4[t];
    // stage a1 tile coalesced: rows d, cols j = jb*128..+128
    for (int t = tid; t < 2048; t += 256) {
        const int dd = t >> 5, c4 = t & 31;
        const float4 v = *(const float4*)(a + (long)dd * NN + jb * 128 + c4 * 4);
        float* dst = sA1 + dd * 129 + c4 * 4;
        dst[0] = v.x; dst[1] = v.y; dst[2] = v.z; dst[3] = v.w;
    }
    __syncthreads();

    const int d = tid & 63, grp = tid >> 6;
    float wReg[64];
    #pragma unroll
    for (int f = 0; f < 64; f++) wReg[f] = sW[f * 64 + d];

    float hs = 0.f;
    for (int rr = 0; rr < 32; rr++) {
        const int r = grp * 32 + rr;
        const int j = jb * 128 + r;
        const float* in = sIn + r * 64;
        float h = 0.f;
        #pragma unroll
        for (int f = 0; f < 64; f++) h = fmaf(in[f], wReg[f], h);
        if (j == 0) h = 0.f;
        float hqf = fminf(fmaxf(h * 2048.f, -32768.f), 32767.f);
        int hq = __float2int_rn(hqf);
        sHi[d * 144 + r] = (char)(hq >> 8);
        sLo[d * 144 + r] = (unsigned char)(hq & 255);
        hs += h;
    }
    sHs[grp * 64 + d] = hs;
    __syncthreads();

    if (tid < 64)
        g_hsumPart[(b * 32 + jb) * 64 + tid] = sHs[tid] + sHs[64 + tid] + sHs[128 + tid] + sHs[192 + tid];

    // score1 pass: 2 threads per row, each sums 32 d's of quantized h * a1
    {
        const int r = tid >> 1, halfd = tid & 1;
        float p = 0.f;
        #pragma unroll
        for (int dd = 0; dd < 32; dd++) {
            const int d2 = halfd * 32 + dd;
            const int hv = 256 * (int)sHi[d2 * 144 + r] + (int)sLo[d2 * 144 + r];
            p = fmaf((float)hv, sA1[d2 * 129 + r], p);
        }
        p += __shfl_xor_sync(0xffffffffu, p, 1);
        if (halfd == 0) g_score1[b * NN + jb * 128 + r] = p * (1.f / 2048.f);
    }

    // write-out planes: 1024 16B chunks
    #pragma unroll
    for (int u = 0; u < 4; u++) {
        const int task = tid + u * 256;
        const int plane = task >> 9;
        const int row = (task >> 3) & 63;
        const int ch = task & 7;
        uint4 v;
        if (plane == 0) v = *(const uint4*)(sHi + row * 144 + ch * 16);
        else            v = *(const uint4*)((const char*)sLo + row * 144 + ch * 16);
        char* base = plane ? (char*)g_hlo : g_hhi;
        *(uint4*)(base + (b * 64 + row) * NN + jb * 128 + ch * 16) = v;
    }
}

// ============================================================================
// k_mask: maskT[i][j] int8.  grid(32, 64) x 256 thr
// ============================================================================
__global__ void __launch_bounds__(256) k_mask(const int* __restrict__ adj)
{
    __shared__ char sT[128 * 80];
    const int mI = blockIdx.x, kt = blockIdx.y;
    const int tid = threadIdx.x;

    #pragma unroll
    for (int u = 0; u < 8; u++) {
        const int cc = tid + u * 256;
        const int jl = cc >> 5, ic = (cc & 31) * 4;
        const int j = kt * 64 + jl;
        int4 v;
        if (j < 4095) v = *(const int4*)(adj + (long)(j + 1) * NN + mI * 128 + ic);
        else v = make_int4(0, 0, 0, 0);
        sT[(ic + 0) * 80 + jl] = (char)(v.x > 0);
        sT[(ic + 1) * 80 + jl] = (char)(v.y > 0);
        sT[(ic + 2) * 80 + jl] = (char)(v.z > 0);
        sT[(ic + 3) * 80 + jl] = (char)(v.w > 0);
    }
    __syncthreads();

    #pragma unroll
    for (int u = 0; u < 2; u++) {
        const int task = tid + u * 256;
        const int il = task >> 2, ch = task & 3;
        uint4 v = *(const uint4*)(sT + il * 80 + ch * 16);
        *(uint4*)(g_maskT + (mI * 128 + il) * NN + kt * 64 + ch * 16) = v;
    }
}

// ============================================================================
// k_hsum_final
// ============================================================================
__global__ void k_hsum_final()
{
    const int idx = blockIdx.x * blockDim.x + threadIdx.x;
    if (idx >= BB * 64) return;
    float s = 0.f;
    #pragma unroll
    for (int rb = 0; rb < 32; rb++) s += g_hsumPart[((idx >> 6) * 32 + rb) * 64 + (idx & 63)];
    g_hsum[idx] = s;
}

// ============================================================================
// k_gemm: int8 mma.sync m16n8k32.  BM=128, BN=128 (2 batches), BK=128,
// 3-stage cp.async, 512 thr (4x4 warps, warp tile 32x32).
// Epilogue: score = score1 + (1/2048)*sum_d(256*Ghi+Glo)*a2, then writes the
// FINAL leaky output (k_out absorbed).
// grid (32 mBlk, 16 nBlk) x 512 thr, dyn smem 165888 (1 CTA/SM)
// ============================================================================
#define STG 55296u        // A 128*144 + Bhi 128*144 + Blo 128*144
#define B_HI_OFF 18432u
#define PLANE_D  18432u   // Blo - Bhi
#define NKT 32

#define IMMA_S8(D, A, B0, B1)                                                 \
    asm volatile("mma.sync.aligned.m16n8k32.row.col.s32.s8.s8.s32 "           \
                 "{%0,%1,%2,%3}, {%4,%5,%6,%7}, {%8,%9}, {%0,%1,%2,%3};\n"    \
                 : "+r"((D)[0]), "+r"((D)[1]), "+r"((D)[2]), "+r"((D)[3])     \
                 : "r"((A)[0]), "r"((A)[1]), "r"((A)[2]), "r"((A)[3]),        \
                   "r"(B0), "r"(B1))
#define IMMA_U8(D, A, B0, B1)                                                 \
    asm volatile("mma.sync.aligned.m16n8k32.row.col.s32.s8.u8.s32 "           \
                 "{%0,%1,%2,%3}, {%4,%5,%6,%7}, {%8,%9}, {%0,%1,%2,%3};\n"    \
                 : "+r"((D)[0]), "+r"((D)[1]), "+r"((D)[2]), "+r"((D)[3])     \
                 : "r"((A)[0]), "r"((A)[1]), "r"((A)[2]), "r"((A)[3]),        \
                   "r"(B0), "r"(B1))

__device__ __forceinline__ void gemm_load_stage(uint32_t sBase, int stage, int kt,
                                                int im0, int in0, int tid)
{
    const int k0 = kt * 128;
    const uint32_t sA = sBase + stage * STG;
    // A: 128 rows x 128 B = 1024 chunks
    #pragma unroll
    for (int u = 0; u < 2; u++) {
        const int c = tid + u * 512;
        const int row = c >> 3, off = c & 7;
        cpa16(sA + row * 144 + off * 16, g_maskT + (im0 + row) * NN + k0 + off * 16);
    }
    // B planes: 128 rows x 128 B each = 1024 chunks each
    #pragma unroll
    for (int u = 0; u < 2; u++) {
        const int c = tid + u * 512;
        const int row = c >> 3, off = c & 7;
        cpa16(sA + B_HI_OFF + row * 144 + off * 16, g_hhi + (in0 + row) * NN + k0 + off * 16);
        cpa16(sA + B_HI_OFF + PLANE_D + row * 144 + off * 16,
              (const char*)g_hlo + (in0 + row) * NN + k0 + off * 16);
    }
}

__global__ void __launch_bounds__(512, 1) k_gemm(const float* __restrict__ a,
                                                 float* __restrict__ out)
{
    extern __shared__ char sm[];
    const uint32_t sBase = smem_u32(sm);
    const int tid = threadIdx.x, warp = tid >> 5, lane = tid & 31;
    const int wm = warp >> 2;            // 0..3 : 32 rows each
    const int wn = warp & 3;             // 0..3 : 32 cols each
    const int im0 = blockIdx.x * 128;    // i base
    const int in0 = blockIdx.y * 128;    // c base (2 batches)

    int accHi[2][4][4], accLo[2][4][4];
    #pragma unroll
    for (int mt = 0; mt < 2; mt++)
        #pragma unroll
        for (int nt = 0; nt < 4; nt++)
            #pragma unroll
            for (int r = 0; r < 4; r++) { accHi[mt][nt][r] = 0; accLo[mt][nt][r] = 0; }

    const int g8 = lane >> 3;
    const int arow = (lane & 7) + 8 * (g8 & 1);
    const int acol = (g8 >> 1) * 16;
    // fused B x4: g0,g1 -> hi plane k0/k16, g2,g3 -> lo plane k0/k16
    const uint32_t bOff = ((uint32_t)(wn * 32 + (lane & 7)) * 144u) +
                          (uint32_t)((g8 & 1) * 16) +
                          (uint32_t)((g8 >> 1) * PLANE_D);

    #pragma unroll
    for (int s = 0; s < 2; s++) {
        gemm_load_stage(sBase, s, s, im0, in0, tid);
        asm volatile("cp.async.commit_group;\n" ::: "memory");
    }

    #pragma unroll 1
    for (int kt = 0; kt < NKT; kt++) {
        asm volatile("cp.async.wait_group 1;\n" ::: "memory");
        __syncthreads();
        if (kt + 2 < NKT) gemm_load_stage(sBase, (kt + 2) % 3, kt + 2, im0, in0, tid);
        asm volatile("cp.async.commit_group;\n" ::: "memory");

        const uint32_t sA  = sBase + (kt % 3) * STG;
        const uint32_t sBh = sA + B_HI_OFF;

        #pragma unroll
        for (int kk = 0; kk < 4; kk++) {
            uint32_t af[2][4];
            #pragma unroll
            for (int mt = 0; mt < 2; mt++) {
                const uint32_t addr = sA + (wm * 32 + mt * 16 + arow) * 144 + kk * 32 + acol;
                asm volatile("ldmatrix.sync.aligned.m8n8.x4.shared.b16 {%0,%1,%2,%3}, [%4];\n"
                             : "=r"(af[mt][0]), "=r"(af[mt][1]),
                               "=r"(af[mt][2]), "=r"(af[mt][3]) : "r"(addr));
            }
            uint32_t bf[4][4];
            #pragma unroll
            for (int nt = 0; nt < 4; nt++) {
                const uint32_t addr = sBh + bOff + nt * 8 * 144 + kk * 32;
                asm volatile("ldmatrix.sync.aligned.m8n8.x4.shared.b16 {%0,%1,%2,%3}, [%4];\n"
                             : "=r"(bf[nt][0]), "=r"(bf[nt][1]),
                               "=r"(bf[nt][2]), "=r"(bf[nt][3]) : "r"(addr));
            }
            #pragma unroll
            for (int mt = 0; mt < 2; mt++)
                #pragma unroll
                for (int nt = 0; nt < 4; nt++) {
                    IMMA_S8(accHi[mt][nt], af[mt], bf[nt][0], bf[nt][1]);
                    IMMA_U8(accLo[mt][nt], af[mt], bf[nt][2], bf[nt][3]);
                }
        }
    }

    // ---- epilogue: score + final output ----
    __syncthreads();
    float* sRed   = (float*)sm;             // [128][4]   2048
    float* sScore = (float*)(sm + 2048);    // [128][2]   1024
    float* sHsum  = (float*)(sm + 3072);    // [2][64]     512
    if (tid < 128) sHsum[tid] = g_hsum[(blockIdx.y * 2 + (tid >> 6)) * 64 + (tid & 63)];

    const int qid = lane >> 2, mem = lane & 3;
    #pragma unroll
    for (int mt = 0; mt < 2; mt++) {
        #pragma unroll
        for (int sub = 0; sub < 2; sub++) {
            const int rowl = wm * 32 + mt * 16 + qid + 8 * sub;
            const int i = im0 + rowl;
            float part = 0.f;
            #pragma unroll
            for (int nt = 0; nt < 4; nt++) {
                #pragma unroll
                for (int cp = 0; cp < 2; cp++) {
                    const int full = (accHi[mt][nt][sub * 2 + cp] << 8) + accLo[mt][nt][sub * 2 + cp];
                    const int dd = (wn * 32 + nt * 8 + 2 * mem + cp) & 63;
                    part = fmaf((float)full, __ldg(&a[(64 + dd) * NN + i]), part);
                }
            }
            part += __shfl_xor_sync(0xffffffffu, part, 1);
            part += __shfl_xor_sync(0xffffffffu, part, 2);
            if (mem == 0) sRed[rowl * 4 + wn] = part;
        }
    }
    __syncthreads();
    if (tid < 256) {
        const int rowl = tid >> 1, bh = tid & 1;
        const int i = im0 + rowl;
        float sc = (sRed[rowl * 4 + 2 * bh] + sRed[rowl * 4 + 2 * bh + 1]) * (1.f / 2048.f)
                   + g_score1[(blockIdx.y * 2 + bh) * NN + i];
        if (i == 0) sc = 0.f;
        sScore[rowl * 2 + bh] = sc;
    }
    __syncthreads();
    {
        const int rowl = tid >> 2, bh = (tid & 3) >> 1, dhalf = tid & 1;
        const int i = im0 + rowl, b = blockIdx.y * 2 + bh;
        const float sc = sScore[rowl * 2 + bh];
        float4* o4 = (float4*)(out + ((long)b * NN + i) * 64 + dhalf * 32);
        const float4* h4 = (const float4*)sHsum + bh * 16 + dhalf * 8;
        #pragma unroll
        for (int k = 0; k < 8; k++) {
            const float4 hv = h4[k];
            float4 v; float t;
            t = sc * hv.x; v.x = (t >= 0.f) ? t : 0.2f * t;
            t = sc * hv.y; v.y = (t >= 0.f) ? t : 0.2f * t;
            t = sc * hv.z; v.z = (t >= 0.f) ? t : 0.2f * t;
            t = sc * hv.w; v.w = (t >= 0.f) ? t : 0.2f * t;
            o4[k] = v;
        }
    }
}

// ============================================================================
extern "C" void kernel_launch(void* const* d_in, const int* in_sizes, int n_in,
                              void* d_out, int out_size)
{
    const float* inp = nullptr; const float* W = nullptr;
    const float* a = nullptr;   const int* adj = nullptr;
    for (int i = 0; i < n_in; i++) {
        switch (in_sizes[i]) {
            case 8388608:  inp = (const float*)d_in[i]; break;
            case 4096:     W   = (const float*)d_in[i]; break;
            case 524288:   a   = (const float*)d_in[i]; break;
            case 16777216: adj = (const int*)d_in[i];   break;
            default: break;
        }
    }
    if (!inp) inp = (const float*)d_in[0];
    if (!W)   W   = (const float*)d_in[1];
    if (!a)   a   = (const float*)d_in[2];
    if (!adj) adj = (const int*)d_in[3];

    cudaFuncSetAttribute(k_prep, cudaFuncAttributeMaxDynamicSharedMemorySize, 101632);
    cudaFuncSetAttribute(k_gemm, cudaFuncAttributeMaxDynamicSharedMemorySize, 3 * STG);

    k_prep<<<dim3(32, 32), 256, 101632>>>(inp, W, a);
    k_mask<<<dim3(32, 64), 256>>>(adj);
    k_hsum_final<<<8, 256>>>();
    k_gemm<<<dim3(32, 16), 512, 3 * STG>>>(a, (float*)d_out);
}